// round 1
// baseline (speedup 1.0000x reference)
#include <cuda_runtime.h>
#include <math.h>

#define BB 8
#define SS 1024
#define HH 768
#define TT 8
#define DDI 64
#define HHID 128
#define KSP 8
#define NHEADS 2
#define FF 256      // HEADS*HID
#define NN 9        // K+1 nodes
#define NC 2        // gaussians
#define DEXT 80     // DI + K*C
#define NEGV 1000000000000.0f

// ---------------- scratch (device globals: no runtime allocation) ----------------
__device__ float g_nodes[BB * NN * HH];
__device__ float g_eproj[BB * 1024];
__device__ float g_cover[BB * SS];
__device__ float g_qk[(size_t)BB * SS * 1024];          // 32 MB
__device__ float g_Qx[(size_t)BB * TT * SS * DEXT];     // 21 MB
__device__ float g_Kx[(size_t)BB * TT * SS * DEXT];     // 21 MB

// ---------------- stage 1: node features (global mean + span means) ----------------
__global__ void k_nodes(const float* __restrict__ hidden, const int* __restrict__ spans) {
    int b = blockIdx.x, tid = threadIdx.x;
    for (int h = tid; h < HH; h += 256) {
        float acc = 0.f;
        for (int s = 0; s < SS; s++) acc += hidden[((size_t)b * SS + s) * HH + h];
        g_nodes[(size_t)(b * NN) * HH + h] = acc * (1.f / SS);
    }
    for (int k = 0; k < KSP; k++) {
        int st = spans[(b * KSP + k) * 3], en = spans[(b * KSP + k) * 3 + 1];
        float len = (float)(en - st + 1);
        for (int h = tid; h < HH; h += 256) {
            float acc = 0.f;
            for (int s = st; s <= en; s++) acc += hidden[((size_t)b * SS + s) * HH + h];
            g_nodes[(size_t)(b * NN + 1 + k) * HH + h] = acc / len;
        }
    }
}

// ---------------- cover counts ----------------
__global__ void k_cover(const int* __restrict__ spans) {
    int idx = blockIdx.x * 256 + threadIdx.x;   // B*S threads
    int b = idx >> 10, s = idx & 1023;
    float c = 0.f;
#pragma unroll
    for (int k = 0; k < KSP; k++) {
        int st = spans[(b * KSP + k) * 3], en = spans[(b * KSP + k) * 3 + 1];
        c += (s >= st && s <= en) ? 1.f : 0.f;
    }
    g_cover[idx] = c;
}

// ---------------- GAT helpers ----------------
__device__ __forceinline__ void gat_srcdst(int tid, const float* h,
                                           const float* __restrict__ aw_src,
                                           const float* __restrict__ aw_dst,
                                           float* sas, float* sad) {
    if (tid < NN * NHEADS) {
        int n = tid / NHEADS, hh = tid % NHEADS;
        float as = 0.f, ad = 0.f;
        for (int d = 0; d < HHID; d++) {
            float v = h[n * FF + hh * HHID + d];
            as += v * aw_src[hh * HHID + d];
            ad += v * aw_dst[hh * HHID + d];
        }
        sas[tid] = as; sad[tid] = ad;
    }
}

__device__ __forceinline__ void gat_attn(int tid, const float* adj, const float* logm,
                                         const float* sas, const float* sad, float* sattn) {
    if (tid < NN * NHEADS) {
        int d = tid / NHEADS, hh = tid % NHEADS;
        float sc[NN]; float mx = -3.4e38f;
#pragma unroll
        for (int s = 0; s < NN; s++) {
            float a = adj[d * NN + s]; float v;
            if (a > 0.f) {
                float e = sad[d * NHEADS + hh] + sas[s * NHEADS + hh];
                e = (e >= 0.f) ? e : 0.2f * e;        // leaky_relu 0.2
                v = e + logm[d * NN + s];
            } else v = -1e30f;
            sc[s] = v; mx = fmaxf(mx, v);
        }
        float sum = 0.f;
#pragma unroll
        for (int s = 0; s < NN; s++) { float p = expf(sc[s] - mx); sc[s] = p; sum += p; }
        float inv = 1.f / sum;
#pragma unroll
        for (int s = 0; s < NN; s++) sattn[(d * NN + s) * NHEADS + hh] = sc[s] * inv;
    }
}

// ---------------- stage 2: GAT x2 + LN + enhanced + e_proj (one block per batch) ----------------
__global__ __launch_bounds__(256) void k_gat(
    const int* __restrict__ spans,
    const float* __restrict__ W1, const float* __restrict__ as1w, const float* __restrict__ ad1w,
    const float* __restrict__ b1, const float* __restrict__ lng, const float* __restrict__ lnb,
    const float* __restrict__ W2, const float* __restrict__ as2w, const float* __restrict__ ad2w,
    const float* __restrict__ b2, const float* __restrict__ dW) {
    int b = blockIdx.x, tid = threadIdx.x;
    __shared__ float adj[NN * NN], logm[NN * NN];
    __shared__ float sh[NN * FF];
    __shared__ float so[NN * FF];
    __shared__ float sattn[NN * NN * NHEADS];
    __shared__ float sas[NN * NHEADS], sad[NN * NHEADS];
    __shared__ float red[256];
    __shared__ float senh[FF];
    __shared__ int sst[KSP], sen[KSP];

    if (tid < KSP) {
        sst[tid] = spans[(b * KSP + tid) * 3];
        sen[tid] = spans[(b * KSP + tid) * 3 + 1];
    }
    __syncthreads();
    if (tid < NN * NN) {
        int d = tid / NN, s = tid % NN;
        float a;
        if (d == 0 || s == 0) a = 1.f;
        else {
            int i = d - 1, j = s - 1;
            bool same = (sst[i] == sst[j]) && (sen[i] == sen[j]);
            bool cont = (sst[j] <= sst[i]) && (sen[i] <= sen[j]) && !same; // span j contains span i
            a = (i == j ? 1.f : 0.f) + (cont ? 2.f : 0.f);
        }
        adj[tid] = a;
        logm[tid] = (a > 0.f) ? logf(fmaxf(a, 1e-20f)) : 0.f;
    }
    __syncthreads();

    // --- GAT layer 1: h1 = nodes @ W1 ---
    {
        float acc[NN];
#pragma unroll
        for (int n = 0; n < NN; n++) acc[n] = 0.f;
        const float* nb = g_nodes + (size_t)b * NN * HH;
        for (int i = 0; i < HH; i++) {
            float w = W1[i * FF + tid];
#pragma unroll
            for (int n = 0; n < NN; n++) acc[n] += nb[n * HH + i] * w;
        }
#pragma unroll
        for (int n = 0; n < NN; n++) sh[n * FF + tid] = acc[n];
    }
    __syncthreads();
    gat_srcdst(tid, sh, as1w, ad1w, sas, sad);
    __syncthreads();
    gat_attn(tid, adj, logm, sas, sad, sattn);
    __syncthreads();
    {   // aggregate + bias + relu -> so
        int hh = tid / HHID;
#pragma unroll
        for (int d = 0; d < NN; d++) {
            float o = 0.f;
#pragma unroll
            for (int s = 0; s < NN; s++) o += sattn[(d * NN + s) * NHEADS + hh] * sh[s * FF + tid];
            o += b1[tid];
            so[d * FF + tid] = fmaxf(o, 0.f);
        }
    }
    __syncthreads();
    // --- layernorm per node: so -> sh ---
    for (int d = 0; d < NN; d++) {
        float x = so[d * FF + tid];
        red[tid] = x; __syncthreads();
        for (int off = 128; off > 0; off >>= 1) { if (tid < off) red[tid] += red[tid + off]; __syncthreads(); }
        float mu = red[0] * (1.f / FF);
        __syncthreads();
        float xc = x - mu;
        red[tid] = xc * xc; __syncthreads();
        for (int off = 128; off > 0; off >>= 1) { if (tid < off) red[tid] += red[tid + off]; __syncthreads(); }
        float var = red[0] * (1.f / FF);
        float rstd = 1.f / sqrtf(var + 1e-5f);
        sh[d * FF + tid] = xc * rstd * lng[tid] + lnb[tid];
        __syncthreads();
    }
    // --- GAT layer 2: h2 = g1 @ W2 -> so ---
    {
        float acc[NN];
#pragma unroll
        for (int n = 0; n < NN; n++) acc[n] = 0.f;
        for (int i = 0; i < FF; i++) {
            float w = W2[i * FF + tid];
#pragma unroll
            for (int n = 0; n < NN; n++) acc[n] += sh[n * FF + i] * w;
        }
        __syncthreads();
#pragma unroll
        for (int n = 0; n < NN; n++) so[n * FF + tid] = acc[n];
    }
    __syncthreads();
    gat_srcdst(tid, so, as2w, ad2w, sas, sad);
    __syncthreads();
    gat_attn(tid, adj, logm, sas, sad, sattn);
    __syncthreads();
    {   // aggregate + bias + relu, then mean over nodes -> senh
        int hh = tid / HHID;
        float msum = 0.f;
#pragma unroll
        for (int d = 0; d < NN; d++) {
            float o = 0.f;
#pragma unroll
            for (int s = 0; s < NN; s++) o += sattn[(d * NN + s) * NHEADS + hh] * so[s * FF + tid];
            o += b2[tid];
            msum += fmaxf(o, 0.f);
        }
        senh[tid] = msum / 9.f;
    }
    __syncthreads();
    // --- e_proj[b] = enhanced @ dense_W[768:1024, :] ---
    for (int r = 0; r < 4; r++) {
        int j = tid + r * 256;
        float a = 0.f;
        for (int i = 0; i < FF; i++) a += senh[i] * dW[(size_t)(HH + i) * 1024 + j];
        g_eproj[b * 1024 + j] = a;
    }
}

// ---------------- stage 3: qk = hidden @ dense_W[0:768] + bias + cover*e_proj ----------------
// M=8192, N=1024, K=768. 64x64 tiles, BK=16, 256 threads, 4x4 micro-tiles.
__global__ __launch_bounds__(256) void k_qkgemm(const float* __restrict__ hidden,
                                                const float* __restrict__ dW,
                                                const float* __restrict__ db) {
    __shared__ float As[16][64];   // [k][m]
    __shared__ float Bs[16][64];   // [k][n]
    int tid = threadIdx.x;
    int tx = tid & 15, ty = tid >> 4;
    int row0 = blockIdx.y * 64, col0 = blockIdx.x * 64;
    int ar = tid >> 2, ak = (tid & 3) * 4;
    int bk = tid >> 4, bc = (tid & 15) * 4;
    const float* Ap = hidden + (size_t)(row0 + ar) * HH + ak;
    const float* Bp = dW + (size_t)bk * 1024 + col0 + bc;
    float acc[4][4] = {};
    for (int k0 = 0; k0 < HH; k0 += 16) {
        float4 av = *(const float4*)Ap;  Ap += 16;
        float4 bv = *(const float4*)Bp;  Bp += (size_t)16 * 1024;
        As[ak + 0][ar] = av.x; As[ak + 1][ar] = av.y; As[ak + 2][ar] = av.z; As[ak + 3][ar] = av.w;
        *(float4*)&Bs[bk][bc] = bv;
        __syncthreads();
#pragma unroll
        for (int k = 0; k < 16; k++) {
            float4 a4 = *(const float4*)&As[k][ty * 4];
            float4 b4 = *(const float4*)&Bs[k][tx * 4];
            float aa[4] = {a4.x, a4.y, a4.z, a4.w};
            float bb[4] = {b4.x, b4.y, b4.z, b4.w};
#pragma unroll
            for (int i = 0; i < 4; i++)
#pragma unroll
                for (int j = 0; j < 4; j++) acc[i][j] += aa[i] * bb[j];
        }
        __syncthreads();
    }
    int b = row0 >> 10;   // 64 | 1024, whole tile in same batch
#pragma unroll
    for (int i = 0; i < 4; i++) {
        int row = row0 + ty * 4 + i;
        float cov = g_cover[row];
        int col = col0 + tx * 4;
        float4 o;
        o.x = acc[i][0] + db[col + 0] + cov * g_eproj[b * 1024 + col + 0];
        o.y = acc[i][1] + db[col + 1] + cov * g_eproj[b * 1024 + col + 1];
        o.z = acc[i][2] + db[col + 2] + cov * g_eproj[b * 1024 + col + 2];
        o.w = acc[i][3] + db[col + 3] + cov * g_eproj[b * 1024 + col + 3];
        *(float4*)&g_qk[(size_t)row * 1024 + col] = o;
    }
}

// ---------------- stage 4: RoPE + pack gaussian rank-16 dims into Q/K (d=80) ----------------
__global__ void k_rope(const int* __restrict__ spans, const float* __restrict__ gc,
                       const float* __restrict__ gs, const float* __restrict__ gw,
                       const float* __restrict__ corr) {
    int s = blockIdx.x, t = blockIdx.y, b = blockIdx.z;
    int d = threadIdx.x;   // 64
    int bt = b * TT + t;
    const float* qrow = g_qk + (size_t)(b * SS + s) * 1024 + t * (2 * DDI);
    float q  = qrow[d],        kk = qrow[DDI + d];
    float qn = qrow[d ^ 1],    kn = qrow[DDI + (d ^ 1)];
    float q2 = (d & 1) ? qn : -qn;   // v2[2i]=-v[2i+1], v2[2i+1]=v[2i]
    float k2 = (d & 1) ? kn : -kn;
    int i = d >> 1;
    double inv = exp((double)i * (-2.0 / (double)DDI) * log(10000.0));
    double ang = (double)s * inv;
    float sn = (float)sin(ang), cs = (float)cos(ang);
    size_t base = ((size_t)bt * SS + s) * DEXT;
    g_Qx[base + d] = q  * cs + q2 * sn;
    g_Kx[base + d] = kk * cs + k2 * sn;
    if (d < KSP * NC) {
        int k = d >> 1, c = d & 1;
        int st = spans[(b * KSP + k) * 3], en = spans[(b * KSP + k) * 3 + 1];
        int ty = spans[(b * KSP + k) * 3 + 2];
        float ctr = gc[c], sg = gs[c], w = gw[c];
        float dxs = ((float)s - (float)st - ctr) / sg;
        float dxe = ((float)s - (float)en - ctr) / sg;
        float Ksr = w * expf(-0.5f * dxs * dxs);
        float Ken = w * expf(-0.5f * dxe * dxe);
        g_Qx[base + DDI + d] = corr[ty * TT + t] * Ksr;
        g_Kx[base + DDI + d] = Ken;
    }
}

// ---------------- stage 5: logits = Q @ K^T (d=80) + mask epilogue ----------------
// grid (S/64, S/64, B*T); 64x64 tiles, full K-slab in smem (80), 4x4 micro-tiles.
__global__ __launch_bounds__(256) void k_attn(const float* __restrict__ mask,
                                              float* __restrict__ out) {
    __shared__ float Qs[DEXT][64];   // [k][m]
    __shared__ float Ks[DEXT][64];   // [k][n]
    int bt = blockIdx.z; int b = bt >> 3;
    int m0 = blockIdx.y * 64, n0 = blockIdx.x * 64;
    int tid = threadIdx.x;
    int tx = tid & 15, ty = tid >> 4;
    const float* Qbase = g_Qx + (size_t)bt * SS * DEXT;
    const float* Kbase = g_Kx + (size_t)bt * SS * DEXT;
    for (int r = tid; r < 64 * 20; r += 256) {
        int row = r / 20, dv = (r % 20) * 4;
        float4 qv = *(const float4*)(Qbase + (size_t)(m0 + row) * DEXT + dv);
        float4 kv = *(const float4*)(Kbase + (size_t)(n0 + row) * DEXT + dv);
        Qs[dv + 0][row] = qv.x; Qs[dv + 1][row] = qv.y; Qs[dv + 2][row] = qv.z; Qs[dv + 3][row] = qv.w;
        Ks[dv + 0][row] = kv.x; Ks[dv + 1][row] = kv.y; Ks[dv + 2][row] = kv.z; Ks[dv + 3][row] = kv.w;
    }
    __syncthreads();
    float acc[4][4] = {};
#pragma unroll
    for (int k = 0; k < DEXT; k++) {
        float4 a4 = *(const float4*)&Qs[k][ty * 4];
        float4 b4 = *(const float4*)&Ks[k][tx * 4];
        float aa[4] = {a4.x, a4.y, a4.z, a4.w};
        float bb[4] = {b4.x, b4.y, b4.z, b4.w};
#pragma unroll
        for (int i = 0; i < 4; i++)
#pragma unroll
            for (int j = 0; j < 4; j++) acc[i][j] += aa[i] * bb[j];
    }
#pragma unroll
    for (int i = 0; i < 4; i++) {
        int m = m0 + ty * 4 + i;
        float v[4];
#pragma unroll
        for (int j = 0; j < 4; j++) {
            int n = n0 + tx * 4 + j;
            float pad = mask[b * SS + n];
            float x = acc[i][j] * pad - (1.f - pad) * NEGV;
            if (m > n) x -= NEGV;       // tril(-1) mask
            v[j] = x * 0.125f;          // 1/sqrt(64)
        }
        *(float4*)&out[((size_t)bt * SS + m) * SS + n0 + tx * 4] =
            make_float4(v[0], v[1], v[2], v[3]);
    }
}

// ---------------- launcher ----------------
extern "C" void kernel_launch(void* const* d_in, const int* in_sizes, int n_in,
                              void* d_out, int out_size) {
    const float* hidden = (const float*)d_in[0];
    const float* amask  = (const float*)d_in[1];
    const int*   spans  = (const int*)  d_in[2];
    const float* W1  = (const float*)d_in[3];
    const float* as1 = (const float*)d_in[4];
    const float* ad1 = (const float*)d_in[5];
    const float* b1  = (const float*)d_in[6];
    const float* lng = (const float*)d_in[7];
    const float* lnb = (const float*)d_in[8];
    const float* W2  = (const float*)d_in[9];
    const float* as2 = (const float*)d_in[10];
    const float* ad2 = (const float*)d_in[11];
    const float* b2  = (const float*)d_in[12];
    const float* dW  = (const float*)d_in[13];
    const float* db  = (const float*)d_in[14];
    const float* gc  = (const float*)d_in[15];
    const float* gs  = (const float*)d_in[16];
    const float* gw  = (const float*)d_in[17];
    const float* corr= (const float*)d_in[18];
    float* out = (float*)d_out;

    k_nodes<<<BB, 256>>>(hidden, spans);
    k_cover<<<(BB * SS) / 256, 256>>>(spans);
    k_gat<<<BB, 256>>>(spans, W1, as1, ad1, b1, lng, lnb, W2, as2, ad2, b2, dW);
    dim3 gq(1024 / 64, (BB * SS) / 64);
    k_qkgemm<<<gq, 256>>>(hidden, dW, db);
    dim3 gr(SS, TT, BB);
    k_rope<<<gr, 64>>>(spans, gc, gs, gw, corr);
    dim3 ga(SS / 64, SS / 64, BB * TT);
    k_attn<<<ga, 256>>>(amask, out);
}

// round 7
// speedup vs baseline: 1.9423x; 1.9423x over previous
#include <cuda_runtime.h>
#include <math.h>

#define BB 8
#define SS 1024
#define HH 768
#define TT 8
#define DDI 64
#define HHID 128
#define KSP 8
#define NHEADS 2
#define FF 256      // HEADS*HID
#define NN 9        // K+1 nodes
#define NC 2        // gaussians
#define DEXT 80     // DI + K*C
#define NEGV 1000000000000.0f

// ---------------- scratch (device globals) ----------------
__device__ float g_nodes[BB * NN * HH];
__device__ float g_eproj[BB * 1024];
__device__ float g_cover[BB * SS];
__device__ float g_Qx[(size_t)BB * TT * SS * DEXT];     // 21 MB
__device__ float g_Kx[(size_t)BB * TT * SS * DEXT];     // 21 MB
__device__ float g_sin[SS * 32];
__device__ float g_cos[SS * 32];

// ---------------- sin/cos tables ----------------
__global__ void k_trig() {
    int idx = blockIdx.x * 256 + threadIdx.x;      // 32768
    int s = idx >> 5, i = idx & 31;
    double inv = exp((double)i * (-2.0 / 64.0) * log(10000.0));
    float ang = (float)s * (float)inv;
    g_sin[idx] = (float)sin((double)ang);
    g_cos[idx] = (float)cos((double)ang);
}

// ---------------- stage 1: node features (coalesced) ----------------
__global__ void k_nodes(const float* __restrict__ hidden, const int* __restrict__ spans) {
    int b = blockIdx.x, chunk = blockIdx.y;
    int h = chunk * 256 + threadIdx.x;
    const float* base = hidden + (size_t)b * SS * HH + h;
    float a0 = 0.f, a1 = 0.f, a2 = 0.f, a3 = 0.f;
    for (int s = 0; s < SS; s += 4) {
        a0 += base[(size_t)s * HH];
        a1 += base[(size_t)(s + 1) * HH];
        a2 += base[(size_t)(s + 2) * HH];
        a3 += base[(size_t)(s + 3) * HH];
    }
    g_nodes[(size_t)(b * NN) * HH + h] = (a0 + a1 + a2 + a3) * (1.f / SS);
    for (int k = 0; k < KSP; k++) {
        int st = spans[(b * KSP + k) * 3], en = spans[(b * KSP + k) * 3 + 1];
        float len = (float)(en - st + 1);
        float acc = 0.f;
        for (int s = st; s <= en; s++) acc += base[(size_t)s * HH];
        g_nodes[(size_t)(b * NN + 1 + k) * HH + h] = acc / len;
    }
}

// ---------------- cover counts ----------------
__global__ void k_cover(const int* __restrict__ spans) {
    int idx = blockIdx.x * 256 + threadIdx.x;   // B*S threads
    int b = idx >> 10, s = idx & 1023;
    float c = 0.f;
#pragma unroll
    for (int k = 0; k < KSP; k++) {
        int st = spans[(b * KSP + k) * 3], en = spans[(b * KSP + k) * 3 + 1];
        c += (s >= st && s <= en) ? 1.f : 0.f;
    }
    g_cover[idx] = c;
}

// ---------------- GAT helpers ----------------
__device__ __forceinline__ void gat_srcdst(int tid, const float* h,
                                           const float* __restrict__ aw_src,
                                           const float* __restrict__ aw_dst,
                                           float* sas, float* sad) {
    if (tid < NN * NHEADS) {
        int n = tid / NHEADS, hh = tid % NHEADS;
        float as = 0.f, ad = 0.f;
        for (int d = 0; d < HHID; d++) {
            float v = h[n * FF + hh * HHID + d];
            as += v * aw_src[hh * HHID + d];
            ad += v * aw_dst[hh * HHID + d];
        }
        sas[tid] = as; sad[tid] = ad;
    }
}

__device__ __forceinline__ void gat_attn(int tid, const float* adj, const float* logm,
                                         const float* sas, const float* sad, float* sattn) {
    if (tid < NN * NHEADS) {
        int d = tid / NHEADS, hh = tid % NHEADS;
        float sc[NN]; float mx = -3.4e38f;
#pragma unroll
        for (int s = 0; s < NN; s++) {
            float a = adj[d * NN + s]; float v;
            if (a > 0.f) {
                float e = sad[d * NHEADS + hh] + sas[s * NHEADS + hh];
                e = (e >= 0.f) ? e : 0.2f * e;
                v = e + logm[d * NN + s];
            } else v = -1e30f;
            sc[s] = v; mx = fmaxf(mx, v);
        }
        float sum = 0.f;
#pragma unroll
        for (int s = 0; s < NN; s++) { float p = expf(sc[s] - mx); sc[s] = p; sum += p; }
        float inv = 1.f / sum;
#pragma unroll
        for (int s = 0; s < NN; s++) sattn[(d * NN + s) * NHEADS + hh] = sc[s] * inv;
    }
}

// ---------------- stage 2: GAT x2 + LN + enhanced + e_proj ----------------
__global__ __launch_bounds__(256) void k_gat(
    const int* __restrict__ spans,
    const float* __restrict__ W1, const float* __restrict__ as1w, const float* __restrict__ ad1w,
    const float* __restrict__ b1, const float* __restrict__ lng, const float* __restrict__ lnb,
    const float* __restrict__ W2, const float* __restrict__ as2w, const float* __restrict__ ad2w,
    const float* __restrict__ b2, const float* __restrict__ dW) {
    int b = blockIdx.x, tid = threadIdx.x;
    __shared__ float adj[NN * NN], logm[NN * NN];
    __shared__ float sh[NN * FF];
    __shared__ float so[NN * FF];
    __shared__ float sattn[NN * NN * NHEADS];
    __shared__ float sas[NN * NHEADS], sad[NN * NHEADS];
    __shared__ float red[256];
    __shared__ float senh[FF];
    __shared__ int sst[KSP], sen[KSP];

    if (tid < KSP) {
        sst[tid] = spans[(b * KSP + tid) * 3];
        sen[tid] = spans[(b * KSP + tid) * 3 + 1];
    }
    __syncthreads();
    if (tid < NN * NN) {
        int d = tid / NN, s = tid % NN;
        float a;
        if (d == 0 || s == 0) a = 1.f;
        else {
            int i = d - 1, j = s - 1;
            bool same = (sst[i] == sst[j]) && (sen[i] == sen[j]);
            bool cont = (sst[j] <= sst[i]) && (sen[i] <= sen[j]) && !same;
            a = (i == j ? 1.f : 0.f) + (cont ? 2.f : 0.f);
        }
        adj[tid] = a;
        logm[tid] = (a > 0.f) ? logf(fmaxf(a, 1e-20f)) : 0.f;
    }
    __syncthreads();

    {
        float acc[NN];
#pragma unroll
        for (int n = 0; n < NN; n++) acc[n] = 0.f;
        const float* nb = g_nodes + (size_t)b * NN * HH;
        for (int i = 0; i < HH; i++) {
            float w = W1[i * FF + tid];
#pragma unroll
            for (int n = 0; n < NN; n++) acc[n] += nb[n * HH + i] * w;
        }
#pragma unroll
        for (int n = 0; n < NN; n++) sh[n * FF + tid] = acc[n];
    }
    __syncthreads();
    gat_srcdst(tid, sh, as1w, ad1w, sas, sad);
    __syncthreads();
    gat_attn(tid, adj, logm, sas, sad, sattn);
    __syncthreads();
    {
        int hh = tid / HHID;
#pragma unroll
        for (int d = 0; d < NN; d++) {
            float o = 0.f;
#pragma unroll
            for (int s = 0; s < NN; s++) o += sattn[(d * NN + s) * NHEADS + hh] * sh[s * FF + tid];
            o += b1[tid];
            so[d * FF + tid] = fmaxf(o, 0.f);
        }
    }
    __syncthreads();
    for (int d = 0; d < NN; d++) {
        float x = so[d * FF + tid];
        red[tid] = x; __syncthreads();
        for (int off = 128; off > 0; off >>= 1) { if (tid < off) red[tid] += red[tid + off]; __syncthreads(); }
        float mu = red[0] * (1.f / FF);
        __syncthreads();
        float xc = x - mu;
        red[tid] = xc * xc; __syncthreads();
        for (int off = 128; off > 0; off >>= 1) { if (tid < off) red[tid] += red[tid + off]; __syncthreads(); }
        float var = red[0] * (1.f / FF);
        float rstd = 1.f / sqrtf(var + 1e-5f);
        sh[d * FF + tid] = xc * rstd * lng[tid] + lnb[tid];
        __syncthreads();
    }
    {
        float acc[NN];
#pragma unroll
        for (int n = 0; n < NN; n++) acc[n] = 0.f;
        for (int i = 0; i < FF; i++) {
            float w = W2[i * FF + tid];
#pragma unroll
            for (int n = 0; n < NN; n++) acc[n] += sh[n * FF + i] * w;
        }
        __syncthreads();
#pragma unroll
        for (int n = 0; n < NN; n++) so[n * FF + tid] = acc[n];
    }
    __syncthreads();
    gat_srcdst(tid, so, as2w, ad2w, sas, sad);
    __syncthreads();
    gat_attn(tid, adj, logm, sas, sad, sattn);
    __syncthreads();
    {
        int hh = tid / HHID;
        float msum = 0.f;
#pragma unroll
        for (int d = 0; d < NN; d++) {
            float o = 0.f;
#pragma unroll
            for (int s = 0; s < NN; s++) o += sattn[(d * NN + s) * NHEADS + hh] * so[s * FF + tid];
            o += b2[tid];
            msum += fmaxf(o, 0.f);
        }
        senh[tid] = msum / 9.f;
    }
    __syncthreads();
    for (int r = 0; r < 4; r++) {
        int j = tid + r * 256;
        float a = 0.f;
        for (int i = 0; i < FF; i++) a += senh[i] * dW[(size_t)(HH + i) * 1024 + j];
        g_eproj[b * 1024 + j] = a;
    }
}

// ---------------- gaussian extra dims (64..79) of Qx/Kx ----------------
__global__ void k_gauss(const int* __restrict__ spans, const float* __restrict__ gc,
                        const float* __restrict__ gs, const float* __restrict__ gw,
                        const float* __restrict__ corr) {
    int idx = blockIdx.x * 256 + threadIdx.x;   // B*S*16
    int b = idx >> 14;
    int s = (idx >> 4) & 1023;
    int kc = idx & 15;
    int k = kc >> 1, c = kc & 1;
    int st = spans[(b * KSP + k) * 3], en = spans[(b * KSP + k) * 3 + 1];
    int ty = spans[(b * KSP + k) * 3 + 2];
    float ctr = gc[c], sg = gs[c], w = gw[c];
    float dxs = ((float)s - (float)st - ctr) / sg;
    float dxe = ((float)s - (float)en - ctr) / sg;
    float Ksr = w * expf(-0.5f * dxs * dxs);
    float Ken = w * expf(-0.5f * dxe * dxe);
#pragma unroll
    for (int t = 0; t < TT; t++) {
        size_t base = ((size_t)(b * TT + t) * SS + s) * DEXT + DDI + kc;
        g_Qx[base] = corr[ty * TT + t] * Ksr;
        g_Kx[base] = Ken;
    }
}

// ---------------- stage 3: qk GEMM (128x128x16, 8x8 micro, double-buffered)
//                  fused bias + cover*eproj + RoPE -> writes g_Qx/g_Kx[0:64] ----
__global__ __launch_bounds__(256) void k_qkgemm(const float* __restrict__ hidden,
                                                const float* __restrict__ dW,
                                                const float* __restrict__ db) {
    __shared__ float As[2][16][128];
    __shared__ float Bs[2][16][128];
    const int tid = threadIdx.x;
    const int tx = tid & 15, ty = tid >> 4;
    const int row0 = blockIdx.y * 128;
    const int col0 = blockIdx.x * 128;
    const int ar = tid >> 1, ak = (tid & 1) * 8;
    const int br = tid >> 5, bc = (tid & 31) * 4;
    const float* Ap = hidden + (size_t)(row0 + ar) * HH + ak;
    const float* Bp = dW + (size_t)br * 1024 + col0 + bc;

    float4 pa0 = *(const float4*)Ap;
    float4 pa1 = *(const float4*)(Ap + 4);
    float4 pb0 = *(const float4*)Bp;
    float4 pb1 = *(const float4*)(Bp + (size_t)8 * 1024);
    As[0][ak + 0][ar] = pa0.x; As[0][ak + 1][ar] = pa0.y; As[0][ak + 2][ar] = pa0.z; As[0][ak + 3][ar] = pa0.w;
    As[0][ak + 4][ar] = pa1.x; As[0][ak + 5][ar] = pa1.y; As[0][ak + 6][ar] = pa1.z; As[0][ak + 7][ar] = pa1.w;
    *(float4*)&Bs[0][br][bc] = pb0;
    *(float4*)&Bs[0][br + 8][bc] = pb1;
    __syncthreads();

    float acc[8][8] = {};
    int cur = 0;
    const int NIT = HH / 16;   // 48
    for (int it = 0; it < NIT; it++) {
        if (it + 1 < NIT) {
            Ap += 16; Bp += (size_t)16 * 1024;
            pa0 = *(const float4*)Ap;
            pa1 = *(const float4*)(Ap + 4);
            pb0 = *(const float4*)Bp;
            pb1 = *(const float4*)(Bp + (size_t)8 * 1024);
        }
#pragma unroll
        for (int kk = 0; kk < 16; kk++) {
            float a[8], bfr[8];
            *(float4*)&a[0]   = *(const float4*)&As[cur][kk][ty * 8];
            *(float4*)&a[4]   = *(const float4*)&As[cur][kk][ty * 8 + 4];
            *(float4*)&bfr[0] = *(const float4*)&Bs[cur][kk][tx * 8];
            *(float4*)&bfr[4] = *(const float4*)&Bs[cur][kk][tx * 8 + 4];
#pragma unroll
            for (int i = 0; i < 8; i++)
#pragma unroll
                for (int j = 0; j < 8; j++) acc[i][j] += a[i] * bfr[j];
        }
        if (it + 1 < NIT) {
            int nxt = cur ^ 1;
            As[nxt][ak + 0][ar] = pa0.x; As[nxt][ak + 1][ar] = pa0.y; As[nxt][ak + 2][ar] = pa0.z; As[nxt][ak + 3][ar] = pa0.w;
            As[nxt][ak + 4][ar] = pa1.x; As[nxt][ak + 5][ar] = pa1.y; As[nxt][ak + 6][ar] = pa1.z; As[nxt][ak + 7][ar] = pa1.w;
            *(float4*)&Bs[nxt][br][bc] = pb0;
            *(float4*)&Bs[nxt][br + 8][bc] = pb1;
            __syncthreads();
            cur = nxt;
        }
    }

    // ---- fused epilogue: bias + cover*eproj + RoPE, write Qx/Kx ----
    const int b = row0 >> 10;
    const int t = blockIdx.x;             // BN=128, N=1024 -> one t-head per block col
    const int dd0 = tx * 8;               // 0..120 within the 128-col head
    const bool isK = dd0 >= 64;
    const int d0 = dd0 & 63;
    float* dst = (isK ? g_Kx : g_Qx);
    float dbj[8], epj[8];
#pragma unroll
    for (int j = 0; j < 8; j++) {
        int col = col0 + dd0 + j;
        dbj[j] = db[col];
        epj[j] = g_eproj[b * 1024 + col];
    }
    const int ibase = d0 >> 1;
#pragma unroll
    for (int i = 0; i < 8; i++) {
        int row = row0 + ty * 8 + i;
        int s = row & 1023;
        float cov = g_cover[row];
        float rv[8];
#pragma unroll
        for (int p = 0; p < 4; p++) {
            float e = acc[i][2 * p]     + dbj[2 * p]     + cov * epj[2 * p];
            float o = acc[i][2 * p + 1] + dbj[2 * p + 1] + cov * epj[2 * p + 1];
            float cs = g_cos[s * 32 + ibase + p];
            float sn = g_sin[s * 32 + ibase + p];
            rv[2 * p]     = e * cs - o * sn;
            rv[2 * p + 1] = o * cs + e * sn;
        }
        size_t base = ((size_t)(b * TT + t) * SS + s) * DEXT + d0;
        *(float4*)&dst[base]     = *(float4*)&rv[0];
        *(float4*)&dst[base + 4] = *(float4*)&rv[4];
    }
}

// ---------------- stage 4: logits = Qx @ Kx^T (d=80), 128x128 tiles ----------------
__global__ __launch_bounds__(256) void k_attn(const float* __restrict__ mask,
                                              float* __restrict__ out) {
    __shared__ float Qs[2][16][128];
    __shared__ float Ks[2][16][128];
    const int bt = blockIdx.z, b = bt >> 3;
    const int m0 = blockIdx.y * 128, n0 = blockIdx.x * 128;
    const int tid = threadIdx.x;
    const int tx = tid & 15, ty = tid >> 4;
    const int ar = tid >> 1, ak = (tid & 1) * 8;
    const float* Qp = g_Qx + ((size_t)bt * SS + m0 + ar) * DEXT + ak;
    const float* Kp = g_Kx + ((size_t)bt * SS + n0 + ar) * DEXT + ak;

    float4 pa0 = *(const float4*)Qp;
    float4 pa1 = *(const float4*)(Qp + 4);
    float4 pb0 = *(const float4*)Kp;
    float4 pb1 = *(const float4*)(Kp + 4);
    Qs[0][ak + 0][ar] = pa0.x; Qs[0][ak + 1][ar] = pa0.y; Qs[0][ak + 2][ar] = pa0.z; Qs[0][ak + 3][ar] = pa0.w;
    Qs[0][ak + 4][ar] = pa1.x; Qs[0][ak + 5][ar] = pa1.y; Qs[0][ak + 6][ar] = pa1.z; Qs[0][ak + 7][ar] = pa1.w;
    Ks[0][ak + 0][ar] = pb0.x; Ks[0][ak + 1][ar] = pb0.y; Ks[0][ak + 2][ar] = pb0.z; Ks[0][ak + 3][ar] = pb0.w;
    Ks[0][ak + 4][ar] = pb1.x; Ks[0][ak + 5][ar] = pb1.y; Ks[0][ak + 6][ar] = pb1.z; Ks[0][ak + 7][ar] = pb1.w;
    __syncthreads();

    float acc[8][8] = {};
    int cur = 0;
    const int NIT = DEXT / 16;   // 5
    for (int it = 0; it < NIT; it++) {
        if (it + 1 < NIT) {
            Qp += 16; Kp += 16;
            pa0 = *(const float4*)Qp;
            pa1 = *(const float4*)(Qp + 4);
            pb0 = *(const float4*)Kp;
            pb1 = *(const float4*)(Kp + 4);
        }
#pragma unroll
        for (int kk = 0; kk < 16; kk++) {
            float a[8], bfr[8];
            *(float4*)&a[0]   = *(const float4*)&Qs[cur][kk][ty * 8];
            *(float4*)&a[4]   = *(const float4*)&Qs[cur][kk][ty * 8 + 4];
            *(float4*)&bfr[0] = *(const float4*)&Ks[cur][kk][tx * 8];
            *(float4*)&bfr[4] = *(const float4*)&Ks[cur][kk][tx * 8 + 4];
#pragma unroll
            for (int i = 0; i < 8; i++)
#pragma unroll
                for (int j = 0; j < 8; j++) acc[i][j] += a[i] * bfr[j];
        }
        if (it + 1 < NIT) {
            int nxt = cur ^ 1;
            Qs[nxt][ak + 0][ar] = pa0.x; Qs[nxt][ak + 1][ar] = pa0.y; Qs[nxt][ak + 2][ar] = pa0.z; Qs[nxt][ak + 3][ar] = pa0.w;
            Qs[nxt][ak + 4][ar] = pa1.x; Qs[nxt][ak + 5][ar] = pa1.y; Qs[nxt][ak + 6][ar] = pa1.z; Qs[nxt][ak + 7][ar] = pa1.w;
            Ks[nxt][ak + 0][ar] = pb0.x; Ks[nxt][ak + 1][ar] = pb0.y; Ks[nxt][ak + 2][ar] = pb0.z; Ks[nxt][ak + 3][ar] = pb0.w;
            Ks[nxt][ak + 4][ar] = pb1.x; Ks[nxt][ak + 5][ar] = pb1.y; Ks[nxt][ak + 6][ar] = pb1.z; Ks[nxt][ak + 7][ar] = pb1.w;
            __syncthreads();
            cur = nxt;
        }
    }

    float pad[8];
#pragma unroll
    for (int j = 0; j < 8; j++) pad[j] = mask[b * SS + n0 + tx * 8 + j];
#pragma unroll
    for (int i = 0; i < 8; i++) {
        int m = m0 + ty * 8 + i;
        float v[8];
#pragma unroll
        for (int j = 0; j < 8; j++) {
            int n = n0 + tx * 8 + j;
            float x = acc[i][j] * pad[j] - (1.f - pad[j]) * NEGV;
            if (m > n) x -= NEGV;
            v[j] = x * 0.125f;
        }
        float* op = out + ((size_t)bt * SS + m) * SS + n0 + tx * 8;
        *(float4*)op       = *(float4*)&v[0];
        *(float4*)(op + 4) = *(float4*)&v[4];
    }
}

// ---------------- launcher ----------------
extern "C" void kernel_launch(void* const* d_in, const int* in_sizes, int n_in,
                              void* d_out, int out_size) {
    const float* hidden = (const float*)d_in[0];
    const float* amask  = (const float*)d_in[1];
    const int*   spans  = (const int*)  d_in[2];
    const float* W1  = (const float*)d_in[3];
    const float* as1 = (const float*)d_in[4];
    const float* ad1 = (const float*)d_in[5];
    const float* b1  = (const float*)d_in[6];
    const float* lng = (const float*)d_in[7];
    const float* lnb = (const float*)d_in[8];
    const float* W2  = (const float*)d_in[9];
    const float* as2 = (const float*)d_in[10];
    const float* ad2 = (const float*)d_in[11];
    const float* b2  = (const float*)d_in[12];
    const float* dW  = (const float*)d_in[13];
    const float* db  = (const float*)d_in[14];
    const float* gc  = (const float*)d_in[15];
    const float* gs  = (const float*)d_in[16];
    const float* gw  = (const float*)d_in[17];
    const float* corr= (const float*)d_in[18];
    float* out = (float*)d_out;

    k_trig<<<128, 256>>>();
    dim3 gn(BB, 3);
    k_nodes<<<gn, 256>>>(hidden, spans);
    k_cover<<<(BB * SS) / 256, 256>>>(spans);
    k_gat<<<BB, 256>>>(spans, W1, as1, ad1, b1, lng, lnb, W2, as2, ad2, b2, dW);
    k_gauss<<<(BB * SS * 16) / 256, 256>>>(spans, gc, gs, gw, corr);
    dim3 gq(1024 / 128, (BB * SS) / 128);
    k_qkgemm<<<gq, 256>>>(hidden, dW, db);
    dim3 ga(SS / 128, SS / 128, BB * TT);
    k_attn<<<ga, 256>>>(amask, out);
}

// round 10
// speedup vs baseline: 2.1035x; 1.0830x over previous
#include <cuda_runtime.h>
#include <math.h>

#define BB 8
#define SS 1024
#define HH 768
#define TT 8
#define DDI 64
#define HHID 128
#define KSP 8
#define NHEADS 2
#define FF 256      // HEADS*HID
#define NN 9        // K+1 nodes
#define NC 2        // gaussians
#define DEXT 80     // DI + K*C
#define NEGV 1000000000000.0f

// ---------------- scratch (device globals) ----------------
__device__ float g_nodes[BB * NN * HH];
__device__ float g_eproj[BB * 1024];
__device__ float g_cover[BB * SS];
__device__ float g_Qx[(size_t)BB * TT * SS * DEXT];     // 21 MB
__device__ float g_Kx[(size_t)BB * TT * SS * DEXT];     // 21 MB
__device__ float g_sin[SS * 32];
__device__ float g_cos[SS * 32];

// ---------------- sin/cos tables ----------------
__global__ void k_trig() {
    int idx = blockIdx.x * 256 + threadIdx.x;      // 32768
    int s = idx >> 5, i = idx & 31;
    double inv = exp((double)i * (-2.0 / 64.0) * log(10000.0));
    float ang = (float)s * (float)inv;
    g_sin[idx] = (float)sin((double)ang);
    g_cos[idx] = (float)cos((double)ang);
}

// ---------------- stage 1: node features (coalesced) ----------------
__global__ void k_nodes(const float* __restrict__ hidden, const int* __restrict__ spans) {
    int b = blockIdx.x, chunk = blockIdx.y;
    int h = chunk * 256 + threadIdx.x;
    const float* base = hidden + (size_t)b * SS * HH + h;
    float a0 = 0.f, a1 = 0.f, a2 = 0.f, a3 = 0.f;
    for (int s = 0; s < SS; s += 4) {
        a0 += base[(size_t)s * HH];
        a1 += base[(size_t)(s + 1) * HH];
        a2 += base[(size_t)(s + 2) * HH];
        a3 += base[(size_t)(s + 3) * HH];
    }
    g_nodes[(size_t)(b * NN) * HH + h] = (a0 + a1 + a2 + a3) * (1.f / SS);
    for (int k = 0; k < KSP; k++) {
        int st = spans[(b * KSP + k) * 3], en = spans[(b * KSP + k) * 3 + 1];
        float len = (float)(en - st + 1);
        float acc = 0.f;
        for (int s = st; s <= en; s++) acc += base[(size_t)s * HH];
        g_nodes[(size_t)(b * NN + 1 + k) * HH + h] = acc / len;
    }
}

// ---------------- cover counts ----------------
__global__ void k_cover(const int* __restrict__ spans) {
    int idx = blockIdx.x * 256 + threadIdx.x;   // B*S threads
    int b = idx >> 10, s = idx & 1023;
    float c = 0.f;
#pragma unroll
    for (int k = 0; k < KSP; k++) {
        int st = spans[(b * KSP + k) * 3], en = spans[(b * KSP + k) * 3 + 1];
        c += (s >= st && s <= en) ? 1.f : 0.f;
    }
    g_cover[idx] = c;
}

// ---------------- GAT helpers ----------------
__device__ __forceinline__ void gat_srcdst(int tid, const float* h,
                                           const float* __restrict__ aw_src,
                                           const float* __restrict__ aw_dst,
                                           float* sas, float* sad) {
    if (tid < NN * NHEADS) {
        int n = tid / NHEADS, hh = tid % NHEADS;
        float as = 0.f, ad = 0.f;
#pragma unroll 8
        for (int d = 0; d < HHID; d++) {
            float v = h[n * FF + hh * HHID + d];
            as += v * aw_src[hh * HHID + d];
            ad += v * aw_dst[hh * HHID + d];
        }
        sas[tid] = as; sad[tid] = ad;
    }
}

__device__ __forceinline__ void gat_attn(int tid, const float* adj, const float* logm,
                                         const float* sas, const float* sad, float* sattn) {
    if (tid < NN * NHEADS) {
        int d = tid / NHEADS, hh = tid % NHEADS;
        float sc[NN]; float mx = -3.4e38f;
#pragma unroll
        for (int s = 0; s < NN; s++) {
            float a = adj[d * NN + s]; float v;
            if (a > 0.f) {
                float e = sad[d * NHEADS + hh] + sas[s * NHEADS + hh];
                e = (e >= 0.f) ? e : 0.2f * e;
                v = e + logm[d * NN + s];
            } else v = -1e30f;
            sc[s] = v; mx = fmaxf(mx, v);
        }
        float sum = 0.f;
#pragma unroll
        for (int s = 0; s < NN; s++) { float p = expf(sc[s] - mx); sc[s] = p; sum += p; }
        float inv = 1.f / sum;
#pragma unroll
        for (int s = 0; s < NN; s++) sattn[(d * NN + s) * NHEADS + hh] = sc[s] * inv;
    }
}

// ---------------- stage 2: GAT x2 + LN + enhanced + e_proj ----------------
// Latency fix (R7): grid=8 kernel was issue=4.7%, regs=32 — one dependent LDG
// per inner iteration. Unroll-8 explicit weight prefetch raises MLP to 8.
__global__ __launch_bounds__(256) void k_gat(
    const int* __restrict__ spans,
    const float* __restrict__ W1, const float* __restrict__ as1w, const float* __restrict__ ad1w,
    const float* __restrict__ b1, const float* __restrict__ lng, const float* __restrict__ lnb,
    const float* __restrict__ W2, const float* __restrict__ as2w, const float* __restrict__ ad2w,
    const float* __restrict__ b2, const float* __restrict__ dW) {
    int b = blockIdx.x, tid = threadIdx.x;
    __shared__ float adj[NN * NN], logm[NN * NN];
    __shared__ float sh[NN * FF];
    __shared__ float so[NN * FF];
    __shared__ float sattn[NN * NN * NHEADS];
    __shared__ float sas[NN * NHEADS], sad[NN * NHEADS];
    __shared__ float red[256];
    __shared__ float senh[FF];
    __shared__ int sst[KSP], sen[KSP];

    if (tid < KSP) {
        sst[tid] = spans[(b * KSP + tid) * 3];
        sen[tid] = spans[(b * KSP + tid) * 3 + 1];
    }
    __syncthreads();
    if (tid < NN * NN) {
        int d = tid / NN, s = tid % NN;
        float a;
        if (d == 0 || s == 0) a = 1.f;
        else {
            int i = d - 1, j = s - 1;
            bool same = (sst[i] == sst[j]) && (sen[i] == sen[j]);
            bool cont = (sst[j] <= sst[i]) && (sen[i] <= sen[j]) && !same;
            a = (i == j ? 1.f : 0.f) + (cont ? 2.f : 0.f);
        }
        adj[tid] = a;
        logm[tid] = (a > 0.f) ? logf(fmaxf(a, 1e-20f)) : 0.f;
    }
    __syncthreads();

    // --- GAT layer 1: h1 = nodes @ W1 (unroll-8 prefetch) ---
    {
        float acc[NN];
#pragma unroll
        for (int n = 0; n < NN; n++) acc[n] = 0.f;
        const float* nb = g_nodes + (size_t)b * NN * HH;
        for (int i = 0; i < HH; i += 8) {
            float w[8];
#pragma unroll
            for (int u = 0; u < 8; u++) w[u] = W1[(size_t)(i + u) * FF + tid];
#pragma unroll
            for (int u = 0; u < 8; u++) {
#pragma unroll
                for (int n = 0; n < NN; n++) acc[n] += nb[n * HH + i + u] * w[u];
            }
        }
#pragma unroll
        for (int n = 0; n < NN; n++) sh[n * FF + tid] = acc[n];
    }
    __syncthreads();
    gat_srcdst(tid, sh, as1w, ad1w, sas, sad);
    __syncthreads();
    gat_attn(tid, adj, logm, sas, sad, sattn);
    __syncthreads();
    {
        int hh = tid / HHID;
#pragma unroll
        for (int d = 0; d < NN; d++) {
            float o = 0.f;
#pragma unroll
            for (int s = 0; s < NN; s++) o += sattn[(d * NN + s) * NHEADS + hh] * sh[s * FF + tid];
            o += b1[tid];
            so[d * FF + tid] = fmaxf(o, 0.f);
        }
    }
    __syncthreads();
    for (int d = 0; d < NN; d++) {
        float x = so[d * FF + tid];
        red[tid] = x; __syncthreads();
        for (int off = 128; off > 0; off >>= 1) { if (tid < off) red[tid] += red[tid + off]; __syncthreads(); }
        float mu = red[0] * (1.f / FF);
        __syncthreads();
        float xc = x - mu;
        red[tid] = xc * xc; __syncthreads();
        for (int off = 128; off > 0; off >>= 1) { if (tid < off) red[tid] += red[tid + off]; __syncthreads(); }
        float var = red[0] * (1.f / FF);
        float rstd = 1.f / sqrtf(var + 1e-5f);
        sh[d * FF + tid] = xc * rstd * lng[tid] + lnb[tid];
        __syncthreads();
    }
    // --- GAT layer 2: h2 = g1 @ W2 (unroll-8 prefetch; g1 rows in smem) ---
    {
        float acc[NN];
#pragma unroll
        for (int n = 0; n < NN; n++) acc[n] = 0.f;
        for (int i = 0; i < FF; i += 8) {
            float w[8];
#pragma unroll
            for (int u = 0; u < 8; u++) w[u] = W2[(size_t)(i + u) * FF + tid];
#pragma unroll
            for (int u = 0; u < 8; u++) {
#pragma unroll
                for (int n = 0; n < NN; n++) acc[n] += sh[n * FF + i + u] * w[u];
            }
        }
        __syncthreads();
#pragma unroll
        for (int n = 0; n < NN; n++) so[n * FF + tid] = acc[n];
    }
    __syncthreads();
    gat_srcdst(tid, so, as2w, ad2w, sas, sad);
    __syncthreads();
    gat_attn(tid, adj, logm, sas, sad, sattn);
    __syncthreads();
    {
        int hh = tid / HHID;
        float msum = 0.f;
#pragma unroll
        for (int d = 0; d < NN; d++) {
            float o = 0.f;
#pragma unroll
            for (int s = 0; s < NN; s++) o += sattn[(d * NN + s) * NHEADS + hh] * so[s * FF + tid];
            o += b2[tid];
            msum += fmaxf(o, 0.f);
        }
        senh[tid] = msum / 9.f;
    }
    __syncthreads();
    // --- e_proj[b] = enhanced @ dense_W[768:1024, :] (unroll-8 prefetch) ---
    for (int r = 0; r < 4; r++) {
        int j = tid + r * 256;
        float a = 0.f;
        for (int i = 0; i < FF; i += 8) {
            float w[8];
#pragma unroll
            for (int u = 0; u < 8; u++) w[u] = dW[(size_t)(HH + i + u) * 1024 + j];
#pragma unroll
            for (int u = 0; u < 8; u++) a += senh[i + u] * w[u];
        }
        g_eproj[b * 1024 + j] = a;
    }
}

// ---------------- gaussian extra dims (64..79) of Qx/Kx ----------------
__global__ void k_gauss(const int* __restrict__ spans, const float* __restrict__ gc,
                        const float* __restrict__ gs, const float* __restrict__ gw,
                        const float* __restrict__ corr) {
    int idx = blockIdx.x * 256 + threadIdx.x;   // B*S*16
    int b = idx >> 14;
    int s = (idx >> 4) & 1023;
    int kc = idx & 15;
    int k = kc >> 1, c = kc & 1;
    int st = spans[(b * KSP + k) * 3], en = spans[(b * KSP + k) * 3 + 1];
    int ty = spans[(b * KSP + k) * 3 + 2];
    float ctr = gc[c], sg = gs[c], w = gw[c];
    float dxs = ((float)s - (float)st - ctr) / sg;
    float dxe = ((float)s - (float)en - ctr) / sg;
    float Ksr = w * expf(-0.5f * dxs * dxs);
    float Ken = w * expf(-0.5f * dxe * dxe);
#pragma unroll
    for (int t = 0; t < TT; t++) {
        size_t base = ((size_t)(b * TT + t) * SS + s) * DEXT + DDI + kc;
        g_Qx[base] = corr[ty * TT + t] * Ksr;
        g_Kx[base] = Ken;
    }
}

// ---------------- stage 3: qk GEMM (128x128x16, 8x8 micro, double-buffered)
//                  fused bias + cover*eproj + RoPE -> writes g_Qx/g_Kx[0:64] ----
__global__ __launch_bounds__(256) void k_qkgemm(const float* __restrict__ hidden,
                                                const float* __restrict__ dW,
                                                const float* __restrict__ db) {
    __shared__ float As[2][16][128];
    __shared__ float Bs[2][16][128];
    const int tid = threadIdx.x;
    const int tx = tid & 15, ty = tid >> 4;
    const int row0 = blockIdx.y * 128;
    const int col0 = blockIdx.x * 128;
    const int ar = tid >> 1, ak = (tid & 1) * 8;
    const int br = tid >> 5, bc = (tid & 31) * 4;
    const float* Ap = hidden + (size_t)(row0 + ar) * HH + ak;
    const float* Bp = dW + (size_t)br * 1024 + col0 + bc;

    float4 pa0 = *(const float4*)Ap;
    float4 pa1 = *(const float4*)(Ap + 4);
    float4 pb0 = *(const float4*)Bp;
    float4 pb1 = *(const float4*)(Bp + (size_t)8 * 1024);
    As[0][ak + 0][ar] = pa0.x; As[0][ak + 1][ar] = pa0.y; As[0][ak + 2][ar] = pa0.z; As[0][ak + 3][ar] = pa0.w;
    As[0][ak + 4][ar] = pa1.x; As[0][ak + 5][ar] = pa1.y; As[0][ak + 6][ar] = pa1.z; As[0][ak + 7][ar] = pa1.w;
    *(float4*)&Bs[0][br][bc] = pb0;
    *(float4*)&Bs[0][br + 8][bc] = pb1;
    __syncthreads();

    float acc[8][8] = {};
    int cur = 0;
    const int NIT = HH / 16;   // 48
    for (int it = 0; it < NIT; it++) {
        if (it + 1 < NIT) {
            Ap += 16; Bp += (size_t)16 * 1024;
            pa0 = *(const float4*)Ap;
            pa1 = *(const float4*)(Ap + 4);
            pb0 = *(const float4*)Bp;
            pb1 = *(const float4*)(Bp + (size_t)8 * 1024);
        }
#pragma unroll
        for (int kk = 0; kk < 16; kk++) {
            float a[8], bfr[8];
            *(float4*)&a[0]   = *(const float4*)&As[cur][kk][ty * 8];
            *(float4*)&a[4]   = *(const float4*)&As[cur][kk][ty * 8 + 4];
            *(float4*)&bfr[0] = *(const float4*)&Bs[cur][kk][tx * 8];
            *(float4*)&bfr[4] = *(const float4*)&Bs[cur][kk][tx * 8 + 4];
#pragma unroll
            for (int i = 0; i < 8; i++)
#pragma unroll
                for (int j = 0; j < 8; j++) acc[i][j] += a[i] * bfr[j];
        }
        if (it + 1 < NIT) {
            int nxt = cur ^ 1;
            As[nxt][ak + 0][ar] = pa0.x; As[nxt][ak + 1][ar] = pa0.y; As[nxt][ak + 2][ar] = pa0.z; As[nxt][ak + 3][ar] = pa0.w;
            As[nxt][ak + 4][ar] = pa1.x; As[nxt][ak + 5][ar] = pa1.y; As[nxt][ak + 6][ar] = pa1.z; As[nxt][ak + 7][ar] = pa1.w;
            *(float4*)&Bs[nxt][br][bc] = pb0;
            *(float4*)&Bs[nxt][br + 8][bc] = pb1;
            __syncthreads();
            cur = nxt;
        }
    }

    // ---- fused epilogue: bias + cover*eproj + RoPE, write Qx/Kx ----
    const int b = row0 >> 10;
    const int t = blockIdx.x;             // BN=128, N=1024 -> one t-head per block col
    const int dd0 = tx * 8;               // 0..120 within the 128-col head
    const bool isK = dd0 >= 64;
    const int d0 = dd0 & 63;
    float* dst = (isK ? g_Kx : g_Qx);
    float dbj[8], epj[8];
#pragma unroll
    for (int j = 0; j < 8; j++) {
        int col = col0 + dd0 + j;
        dbj[j] = db[col];
        epj[j] = g_eproj[b * 1024 + col];
    }
    const int ibase = d0 >> 1;
#pragma unroll
    for (int i = 0; i < 8; i++) {
        int row = row0 + ty * 8 + i;
        int s = row & 1023;
        float cov = g_cover[row];
        float rv[8];
#pragma unroll
        for (int p = 0; p < 4; p++) {
            float e = acc[i][2 * p]     + dbj[2 * p]     + cov * epj[2 * p];
            float o = acc[i][2 * p + 1] + dbj[2 * p + 1] + cov * epj[2 * p + 1];
            float cs = g_cos[s * 32 + ibase + p];
            float sn = g_sin[s * 32 + ibase + p];
            rv[2 * p]     = e * cs - o * sn;
            rv[2 * p + 1] = o * cs + e * sn;
        }
        size_t base = ((size_t)(b * TT + t) * SS + s) * DEXT + d0;
        *(float4*)&dst[base]     = *(float4*)&rv[0];
        *(float4*)&dst[base + 4] = *(float4*)&rv[4];
    }
}

// ---------------- stage 4: logits = Qx @ Kx^T (d=80), 128x128 tiles ----------------
__global__ __launch_bounds__(256) void k_attn(const float* __restrict__ mask,
                                              float* __restrict__ out) {
    __shared__ float Qs[2][16][128];
    __shared__ float Ks[2][16][128];
    const int bt = blockIdx.z, b = bt >> 3;
    const int m0 = blockIdx.y * 128, n0 = blockIdx.x * 128;
    const int tid = threadIdx.x;
    const int tx = tid & 15, ty = tid >> 4;
    const int ar = tid >> 1, ak = (tid & 1) * 8;
    const float* Qp = g_Qx + ((size_t)bt * SS + m0 + ar) * DEXT + ak;
    const float* Kp = g_Kx + ((size_t)bt * SS + n0 + ar) * DEXT + ak;

    float4 pa0 = *(const float4*)Qp;
    float4 pa1 = *(const float4*)(Qp + 4);
    float4 pb0 = *(const float4*)Kp;
    float4 pb1 = *(const float4*)(Kp + 4);
    Qs[0][ak + 0][ar] = pa0.x; Qs[0][ak + 1][ar] = pa0.y; Qs[0][ak + 2][ar] = pa0.z; Qs[0][ak + 3][ar] = pa0.w;
    Qs[0][ak + 4][ar] = pa1.x; Qs[0][ak + 5][ar] = pa1.y; Qs[0][ak + 6][ar] = pa1.z; Qs[0][ak + 7][ar] = pa1.w;
    Ks[0][ak + 0][ar] = pb0.x; Ks[0][ak + 1][ar] = pb0.y; Ks[0][ak + 2][ar] = pb0.z; Ks[0][ak + 3][ar] = pb0.w;
    Ks[0][ak + 4][ar] = pb1.x; Ks[0][ak + 5][ar] = pb1.y; Ks[0][ak + 6][ar] = pb1.z; Ks[0][ak + 7][ar] = pb1.w;
    __syncthreads();

    float acc[8][8] = {};
    int cur = 0;
    const int NIT = DEXT / 16;   // 5
    for (int it = 0; it < NIT; it++) {
        if (it + 1 < NIT) {
            Qp += 16; Kp += 16;
            pa0 = *(const float4*)Qp;
            pa1 = *(const float4*)(Qp + 4);
            pb0 = *(const float4*)Kp;
            pb1 = *(const float4*)(Kp + 4);
        }
#pragma unroll
        for (int kk = 0; kk < 16; kk++) {
            float a[8], bfr[8];
            *(float4*)&a[0]   = *(const float4*)&Qs[cur][kk][ty * 8];
            *(float4*)&a[4]   = *(const float4*)&Qs[cur][kk][ty * 8 + 4];
            *(float4*)&bfr[0] = *(const float4*)&Ks[cur][kk][tx * 8];
            *(float4*)&bfr[4] = *(const float4*)&Ks[cur][kk][tx * 8 + 4];
#pragma unroll
            for (int i = 0; i < 8; i++)
#pragma unroll
                for (int j = 0; j < 8; j++) acc[i][j] += a[i] * bfr[j];
        }
        if (it + 1 < NIT) {
            int nxt = cur ^ 1;
            Qs[nxt][ak + 0][ar] = pa0.x; Qs[nxt][ak + 1][ar] = pa0.y; Qs[nxt][ak + 2][ar] = pa0.z; Qs[nxt][ak + 3][ar] = pa0.w;
            Qs[nxt][ak + 4][ar] = pa1.x; Qs[nxt][ak + 5][ar] = pa1.y; Qs[nxt][ak + 6][ar] = pa1.z; Qs[nxt][ak + 7][ar] = pa1.w;
            Ks[nxt][ak + 0][ar] = pb0.x; Ks[nxt][ak + 1][ar] = pb0.y; Ks[nxt][ak + 2][ar] = pb0.z; Ks[nxt][ak + 3][ar] = pb0.w;
            Ks[nxt][ak + 4][ar] = pb1.x; Ks[nxt][ak + 5][ar] = pb1.y; Ks[nxt][ak + 6][ar] = pb1.z; Ks[nxt][ak + 7][ar] = pb1.w;
            __syncthreads();
            cur = nxt;
        }
    }

    float pad[8];
#pragma unroll
    for (int j = 0; j < 8; j++) pad[j] = mask[b * SS + n0 + tx * 8 + j];
#pragma unroll
    for (int i = 0; i < 8; i++) {
        int m = m0 + ty * 8 + i;
        float v[8];
#pragma unroll
        for (int j = 0; j < 8; j++) {
            int n = n0 + tx * 8 + j;
            float x = acc[i][j] * pad[j] - (1.f - pad[j]) * NEGV;
            if (m > n) x -= NEGV;
            v[j] = x * 0.125f;
        }
        float* op = out + ((size_t)bt * SS + m) * SS + n0 + tx * 8;
        *(float4*)op       = *(float4*)&v[0];
        *(float4*)(op + 4) = *(float4*)&v[4];
    }
}

// ---------------- launcher ----------------
extern "C" void kernel_launch(void* const* d_in, const int* in_sizes, int n_in,
                              void* d_out, int out_size) {
    const float* hidden = (const float*)d_in[0];
    const float* amask  = (const float*)d_in[1];
    const int*   spans  = (const int*)  d_in[2];
    const float* W1  = (const float*)d_in[3];
    const float* as1 = (const float*)d_in[4];
    const float* ad1 = (const float*)d_in[5];
    const float* b1  = (const float*)d_in[6];
    const float* lng = (const float*)d_in[7];
    const float* lnb = (const float*)d_in[8];
    const float* W2  = (const float*)d_in[9];
    const float* as2 = (const float*)d_in[10];
    const float* ad2 = (const float*)d_in[11];
    const float* b2  = (const float*)d_in[12];
    const float* dW  = (const float*)d_in[13];
    const float* db  = (const float*)d_in[14];
    const float* gc  = (const float*)d_in[15];
    const float* gs  = (const float*)d_in[16];
    const float* gw  = (const float*)d_in[17];
    const float* corr= (const float*)d_in[18];
    float* out = (float*)d_out;

    k_trig<<<128, 256>>>();
    dim3 gn(BB, 3);
    k_nodes<<<gn, 256>>>(hidden, spans);
    k_cover<<<(BB * SS) / 256, 256>>>(spans);
    k_gat<<<BB, 256>>>(spans, W1, as1, ad1, b1, lng, lnb, W2, as2, ad2, b2, dW);
    k_gauss<<<(BB * SS * 16) / 256, 256>>>(spans, gc, gs, gw, corr);
    dim3 gq(1024 / 128, (BB * SS) / 128);
    k_qkgemm<<<gq, 256>>>(hidden, dW, db);
    dim3 ga(SS / 128, SS / 128, BB * TT);
    k_attn<<<ga, 256>>>(amask, out);
}